// round 1
// baseline (speedup 1.0000x reference)
#include <cuda_runtime.h>
#include <cstdint>

// Problem constants (fixed shapes from reference)
constexpr int TOK = 16384;   // B*S
constexpr int DM  = 1024;    // model dim
constexpr int FM  = 4096;    // ffn dim
constexpr int NE  = 8;       // experts
constexpr int CAP = 2048;    // capacity per expert

// -------- device scratch (no allocations allowed) --------
__device__ int   g_eidx[TOK];
__device__ float g_ptok[TOK];
__device__ int   g_dispatch[NE * CAP];
__device__ int   g_cnt[NE];
__device__ float g_h[(size_t)NE * CAP * FM];   // 256 MiB intermediate

// ============================================================
// 1) Router: logits = x @ Wr, argmax (first-max), p_tok = softmax max
//    warp-per-token, Wr staged transposed in smem.
// ============================================================
__global__ void router_kernel(const float* __restrict__ x,
                              const float* __restrict__ Wr) {
    __shared__ float sW[NE * DM];  // 32 KB, sW[e*DM + d]
    const int tid = threadIdx.x;   // 256 threads
    for (int i = tid; i < NE * DM; i += 256) {
        int d = i >> 3, e = i & 7;
        sW[e * DM + d] = Wr[i];
    }
    __syncthreads();

    const int warp = tid >> 5, lane = tid & 31;
    const int tokBase = blockIdx.x * 32 + warp * 4;

    for (int tt = 0; tt < 4; tt++) {
        const int t = tokBase + tt;
        const float* xp = x + (size_t)t * DM;
        float acc[NE];
#pragma unroll
        for (int e = 0; e < NE; e++) acc[e] = 0.f;

        for (int k = 0; k < DM / 32; k++) {
            float xv = xp[k * 32 + lane];
#pragma unroll
            for (int e = 0; e < NE; e++)
                acc[e] += xv * sW[e * DM + k * 32 + lane];
        }
#pragma unroll
        for (int e = 0; e < NE; e++) {
#pragma unroll
            for (int off = 16; off; off >>= 1)
                acc[e] += __shfl_xor_sync(0xffffffffu, acc[e], off);
        }
        if (lane == 0) {
            float best = acc[0]; int bi = 0;
#pragma unroll
            for (int e = 1; e < NE; e++)
                if (acc[e] > best) { best = acc[e]; bi = e; }
            float s = 0.f;
#pragma unroll
            for (int e = 0; e < NE; e++) s += expf(acc[e] - best);
            g_ptok[t] = 1.f / s;
            g_eidx[t] = bi;
        }
    }
}

// ============================================================
// 2) Deterministic rank + dispatch build (single block).
//    rank = # earlier tokens (by flat index) with the same expert.
// ============================================================
__global__ void rank_kernel() {
    __shared__ int cnts[256 * NE];
    const int tid = threadIdx.x;           // 256 threads
    const int base = tid * (TOK / 256);    // 64 tokens per thread

    int c[NE];
#pragma unroll
    for (int e = 0; e < NE; e++) c[e] = 0;
    for (int i = 0; i < TOK / 256; i++) c[g_eidx[base + i]]++;
#pragma unroll
    for (int e = 0; e < NE; e++) cnts[tid * NE + e] = c[e];
    __syncthreads();

    if (tid < NE) {
        int run = 0;
        for (int j = 0; j < 256; j++) {
            int v = cnts[j * NE + tid];
            cnts[j * NE + tid] = run;
            run += v;
        }
        g_cnt[tid] = run < CAP ? run : CAP;
    }
    __syncthreads();

    int r[NE];
#pragma unroll
    for (int e = 0; e < NE; e++) r[e] = cnts[tid * NE + e];
    for (int i = 0; i < TOK / 256; i++) {
        int t = base + i;
        int e = g_eidx[t];
        int rk = r[e]++;
        if (rk < CAP) g_dispatch[e * CAP + rk] = t;
    }
}

// ============================================================
// 3) zero output (dropped tokens must be exactly 0; d_out is poisoned)
// ============================================================
__global__ void zero_kernel(float4* __restrict__ y, int n4) {
    int i = blockIdx.x * blockDim.x + threadIdx.x;
    if (i < n4) y[i] = make_float4(0.f, 0.f, 0.f, 0.f);
}

// ============================================================
// SGEMM tiles: 128x128x8, 256 threads, 8x8 split-quadrant microtile
// ============================================================
constexpr int BM = 128, BN = 128, BK = 8;

// GEMM1: h[e] = relu(x[dispatch[e]] @ W1[e])   (gather fused)
__global__ __launch_bounds__(256, 2)
void gemm1_kernel(const float* __restrict__ x, const float* __restrict__ W1) {
    const int e = blockIdx.z;
    const int n_cnt = g_cnt[e];
    const int row0 = blockIdx.y * BM;
    if (row0 >= n_cnt) return;

    const float* Bg = W1 + (size_t)e * DM * FM + blockIdx.x * BN;
    float* Hg = g_h + (size_t)e * CAP * FM + (size_t)row0 * FM + blockIdx.x * BN;

    __shared__ float As[BK][BM];
    __shared__ float Bs[BK][BN];
    __shared__ int rowTok[BM];

    const int tid = threadIdx.x;
    if (tid < BM) {
        int r = row0 + tid;
        rowTok[tid] = (r < n_cnt) ? g_dispatch[e * CAP + r] : -1;
    }
    __syncthreads();

    const int a_row = tid >> 1;
    const int a_k4  = (tid & 1) * 4;
    const int b_k   = tid >> 5;
    const int b_n4  = (tid & 31) * 4;
    const int tokA  = rowTok[a_row];
    const float* Ap = x + (size_t)(tokA >= 0 ? tokA : 0) * DM + a_k4;
    const float* Bp = Bg + (size_t)b_k * FM + b_n4;

    const int tx = tid & 15, ty = tid >> 4;

    float acc[8][8];
#pragma unroll
    for (int i = 0; i < 8; i++)
#pragma unroll
        for (int j = 0; j < 8; j++) acc[i][j] = 0.f;

    float4 av = (tokA >= 0) ? *(const float4*)(Ap) : make_float4(0, 0, 0, 0);
    float4 bv = *(const float4*)(Bp);

    for (int kt = 0; kt < DM; kt += BK) {
        __syncthreads();
        As[a_k4 + 0][a_row] = av.x;
        As[a_k4 + 1][a_row] = av.y;
        As[a_k4 + 2][a_row] = av.z;
        As[a_k4 + 3][a_row] = av.w;
        *(float4*)&Bs[b_k][b_n4] = bv;
        __syncthreads();

        if (kt + BK < DM) {  // prefetch next tiles
            av = (tokA >= 0) ? *(const float4*)(Ap + kt + BK) : make_float4(0, 0, 0, 0);
            bv = *(const float4*)(Bp + (size_t)(kt + BK) * FM);
        }

#pragma unroll
        for (int k = 0; k < BK; k++) {
            float a[8], b[8];
            *(float4*)&a[0] = *(const float4*)&As[k][ty * 4];
            *(float4*)&a[4] = *(const float4*)&As[k][64 + ty * 4];
            *(float4*)&b[0] = *(const float4*)&Bs[k][tx * 4];
            *(float4*)&b[4] = *(const float4*)&Bs[k][64 + tx * 4];
#pragma unroll
            for (int i = 0; i < 8; i++)
#pragma unroll
                for (int j = 0; j < 8; j++)
                    acc[i][j] += a[i] * b[j];
        }
    }

#pragma unroll
    for (int i = 0; i < 8; i++) {
        int row = (i < 4) ? (ty * 4 + i) : (64 + ty * 4 + i - 4);
        float* hp = Hg + (size_t)row * FM;
        float4 v0, v1;
        v0.x = fmaxf(acc[i][0], 0.f); v0.y = fmaxf(acc[i][1], 0.f);
        v0.z = fmaxf(acc[i][2], 0.f); v0.w = fmaxf(acc[i][3], 0.f);
        v1.x = fmaxf(acc[i][4], 0.f); v1.y = fmaxf(acc[i][5], 0.f);
        v1.z = fmaxf(acc[i][6], 0.f); v1.w = fmaxf(acc[i][7], 0.f);
        *(float4*)(hp + tx * 4)      = v0;
        *(float4*)(hp + 64 + tx * 4) = v1;
    }
}

// GEMM2: y[dispatch[e]] = p_tok * (h[e] @ W2[e])   (scale+scatter fused)
__global__ __launch_bounds__(256, 2)
void gemm2_kernel(const float* __restrict__ W2, float* __restrict__ y) {
    const int e = blockIdx.z;
    const int n_cnt = g_cnt[e];
    const int row0 = blockIdx.y * BM;
    if (row0 >= n_cnt) return;

    const float* Ag = g_h + (size_t)e * CAP * FM + (size_t)row0 * FM;
    const float* Bg = W2 + (size_t)e * FM * DM + blockIdx.x * BN;

    __shared__ float As[BK][BM];
    __shared__ float Bs[BK][BN];

    const int tid = threadIdx.x;
    const int a_row = tid >> 1;
    const int a_k4  = (tid & 1) * 4;
    const int b_k   = tid >> 5;
    const int b_n4  = (tid & 31) * 4;
    const float* Ap = Ag + (size_t)a_row * FM + a_k4;
    const float* Bp = Bg + (size_t)b_k * DM + b_n4;

    const int tx = tid & 15, ty = tid >> 4;

    float acc[8][8];
#pragma unroll
    for (int i = 0; i < 8; i++)
#pragma unroll
        for (int j = 0; j < 8; j++) acc[i][j] = 0.f;

    float4 av = *(const float4*)(Ap);
    float4 bv = *(const float4*)(Bp);

    for (int kt = 0; kt < FM; kt += BK) {
        __syncthreads();
        As[a_k4 + 0][a_row] = av.x;
        As[a_k4 + 1][a_row] = av.y;
        As[a_k4 + 2][a_row] = av.z;
        As[a_k4 + 3][a_row] = av.w;
        *(float4*)&Bs[b_k][b_n4] = bv;
        __syncthreads();

        if (kt + BK < FM) {
            av = *(const float4*)(Ap + kt + BK);
            bv = *(const float4*)(Bp + (size_t)(kt + BK) * DM);
        }

#pragma unroll
        for (int k = 0; k < BK; k++) {
            float a[8], b[8];
            *(float4*)&a[0] = *(const float4*)&As[k][ty * 4];
            *(float4*)&a[4] = *(const float4*)&As[k][64 + ty * 4];
            *(float4*)&b[0] = *(const float4*)&Bs[k][tx * 4];
            *(float4*)&b[4] = *(const float4*)&Bs[k][64 + tx * 4];
#pragma unroll
            for (int i = 0; i < 8; i++)
#pragma unroll
                for (int j = 0; j < 8; j++)
                    acc[i][j] += a[i] * b[j];
        }
    }

#pragma unroll
    for (int i = 0; i < 8; i++) {
        int row = (i < 4) ? (ty * 4 + i) : (64 + ty * 4 + i - 4);
        int r = row0 + row;
        if (r < n_cnt) {
            int tok = g_dispatch[e * CAP + r];
            float p = g_ptok[tok];
            float* yp = y + (size_t)tok * DM + blockIdx.x * BN;
            float4 v0, v1;
            v0.x = acc[i][0] * p; v0.y = acc[i][1] * p;
            v0.z = acc[i][2] * p; v0.w = acc[i][3] * p;
            v1.x = acc[i][4] * p; v1.y = acc[i][5] * p;
            v1.z = acc[i][6] * p; v1.w = acc[i][7] * p;
            *(float4*)(yp + tx * 4)      = v0;
            *(float4*)(yp + 64 + tx * 4) = v1;
        }
    }
}

// ============================================================
extern "C" void kernel_launch(void* const* d_in, const int* in_sizes, int n_in,
                              void* d_out, int out_size) {
    (void)in_sizes; (void)n_in; (void)out_size;
    const float* x  = (const float*)d_in[0];
    const float* Wr = (const float*)d_in[1];
    const float* W1 = (const float*)d_in[2];
    const float* W2 = (const float*)d_in[3];
    float* y = (float*)d_out;

    router_kernel<<<TOK / 32, 256>>>(x, Wr);
    rank_kernel<<<1, 256>>>();

    const int n4 = TOK * DM / 4;
    zero_kernel<<<(n4 + 255) / 256, 256>>>((float4*)y, n4);

    gemm1_kernel<<<dim3(FM / BN, CAP / BM, NE), 256>>>(x, W1);
    gemm2_kernel<<<dim3(DM / BN, CAP / BM, NE), 256>>>(W2, y);
}